// round 2
// baseline (speedup 1.0000x reference)
#include <cuda_runtime.h>
#include <math.h>

namespace {
constexpr int B  = 2;
constexpr int T  = 2048;
constexpr int D  = 1024;
constexpr int H  = 16;
constexpr int DH = 64;
constexpr int D3 = 3 * D;
constexpr int M  = B * T;      // 4096
}

// Scratch (allocation-free rule: __device__ globals)
__device__ float g_qkv[(size_t)M * D3];   // [M, 3D]
__device__ float g_att[(size_t)M * D];    // [M, D]

// ---------------------------------------------------------------------------
// C[M,N] = A[M,K] @ W[K,N] + bias[N]   (128x128 tile, BK=8, 8x8 per thread)
// ---------------------------------------------------------------------------
__global__ __launch_bounds__(256) void sgemm_bias(
    const float* __restrict__ A, const float* __restrict__ W,
    const float* __restrict__ bias, float* __restrict__ C,
    int Mm, int Nn, int Kk)
{
    __shared__ float As[8][132];   // k-major, padded
    __shared__ float Bs[8][128];

    const int tid = threadIdx.x;
    const int tx = tid & 15, ty = tid >> 4;
    const int m0 = blockIdx.y * 128;
    const int n0 = blockIdx.x * 128;

    float acc[8][8];
#pragma unroll
    for (int i = 0; i < 8; i++)
#pragma unroll
        for (int j = 0; j < 8; j++) acc[i][j] = 0.f;

    const int arow = tid >> 1;          // 0..127
    const int acol = (tid & 1) * 4;     // 0 or 4
    const int brow = tid >> 5;          // 0..7
    const int bcol = (tid & 31) * 4;    // 0..124

    for (int k0 = 0; k0 < Kk; k0 += 8) {
        float4 av = *(const float4*)&A[(size_t)(m0 + arow) * Kk + k0 + acol];
        As[acol + 0][arow] = av.x;
        As[acol + 1][arow] = av.y;
        As[acol + 2][arow] = av.z;
        As[acol + 3][arow] = av.w;
        float4 bv = *(const float4*)&W[(size_t)(k0 + brow) * Nn + n0 + bcol];
        *(float4*)&Bs[brow][bcol] = bv;
        __syncthreads();
#pragma unroll
        for (int kk = 0; kk < 8; kk++) {
            float a[8], b[8];
#pragma unroll
            for (int i = 0; i < 8; i++) a[i] = As[kk][ty * 8 + i];
#pragma unroll
            for (int j = 0; j < 8; j++) b[j] = Bs[kk][tx * 8 + j];
#pragma unroll
            for (int i = 0; i < 8; i++)
#pragma unroll
                for (int j = 0; j < 8; j++) acc[i][j] += a[i] * b[j];
        }
        __syncthreads();
    }

    float bb[8];
#pragma unroll
    for (int j = 0; j < 8; j++) bb[j] = bias[n0 + tx * 8 + j];
#pragma unroll
    for (int i = 0; i < 8; i++) {
        float* cp = &C[(size_t)(m0 + ty * 8 + i) * Nn + n0 + tx * 8];
        float4 v0 = make_float4(acc[i][0] + bb[0], acc[i][1] + bb[1],
                                acc[i][2] + bb[2], acc[i][3] + bb[3]);
        float4 v1 = make_float4(acc[i][4] + bb[4], acc[i][5] + bb[5],
                                acc[i][6] + bb[6], acc[i][7] + bb[7]);
        *(float4*)&cp[0] = v0;
        *(float4*)&cp[4] = v1;
    }
}

// ---------------------------------------------------------------------------
// Flash attention, fp32, causal. One CTA per (b, h, 64-query tile). Bk = 64.
// smem: Qt[d][i] (64x64), KPt (64x68: K^T then P^T), Vs[j][d] (64x64), stats.
// ---------------------------------------------------------------------------
__global__ __launch_bounds__(256) void flash_attn(
    const float* __restrict__ qkv, float* __restrict__ out)
{
    extern __shared__ float sm[];
    float* Qt   = sm;                 // [64][64]   Qt[d*64 + i]
    float* KPt  = Qt + 64 * 64;       // [64][68]   Kt[d][j] -> Pt[j][i]
    float* Vs   = KPt + 64 * 68;      // [64][64]   Vs[j][d]
    float* mrow = Vs + 64 * 64;       // [64]
    float* lrow = mrow + 64;          // [64]
    float* arow = lrow + 64;          // [64] alpha

    const int tid = threadIdx.x;
    const int tx = tid & 15, ty = tid >> 4;
    const int qt = blockIdx.x, h = blockIdx.y, b = blockIdx.z;
    const int qi0 = qt * 64;
    const float scale = 0.125f;       // 1/sqrt(64)

    const size_t base = (size_t)(b * T) * D3 + (size_t)h * DH;

    // load Q tile transposed: Qt[d][i]
#pragma unroll
    for (int e = 0; e < 4; e++) {
        int ff  = tid + 256 * e;      // 0..1023
        int row = ff >> 4;            // 0..63
        int c4  = (ff & 15) * 4;      // 0..60
        float4 v = *(const float4*)&qkv[base + (size_t)(qi0 + row) * D3 + c4];
        Qt[(c4 + 0) * 64 + row] = v.x;
        Qt[(c4 + 1) * 64 + row] = v.y;
        Qt[(c4 + 2) * 64 + row] = v.z;
        Qt[(c4 + 3) * 64 + row] = v.w;
    }
    if (tid < 64) { mrow[tid] = -3.0e38f; lrow[tid] = 0.f; }

    float o[4][4];
#pragma unroll
    for (int i = 0; i < 4; i++)
#pragma unroll
        for (int j = 0; j < 4; j++) o[i][j] = 0.f;

    __syncthreads();

    for (int k0 = 0; k0 <= qi0; k0 += 64) {
        // load K (transposed) and V tiles
#pragma unroll
        for (int e = 0; e < 4; e++) {
            int ff  = tid + 256 * e;
            int row = ff >> 4;
            int c4  = (ff & 15) * 4;
            size_t g = base + (size_t)(k0 + row) * D3 + c4;
            float4 kv = *(const float4*)&qkv[g + D];       // K
            KPt[(c4 + 0) * 68 + row] = kv.x;
            KPt[(c4 + 1) * 68 + row] = kv.y;
            KPt[(c4 + 2) * 68 + row] = kv.z;
            KPt[(c4 + 3) * 68 + row] = kv.w;
            float4 vv = *(const float4*)&qkv[g + 2 * D];   // V
            *(float4*)&Vs[row * 64 + c4] = vv;
        }
        __syncthreads();

        // S = Q K^T (regs)
        float s[4][4];
#pragma unroll
        for (int i = 0; i < 4; i++)
#pragma unroll
            for (int j = 0; j < 4; j++) s[i][j] = 0.f;
#pragma unroll 8
        for (int kk = 0; kk < 64; kk++) {
            float4 qa = *(const float4*)&Qt[kk * 64 + ty * 4];
            float4 kb = *(const float4*)&KPt[kk * 68 + tx * 4];
            float a[4] = {qa.x, qa.y, qa.z, qa.w};
            float bb[4] = {kb.x, kb.y, kb.z, kb.w};
#pragma unroll
            for (int i = 0; i < 4; i++)
#pragma unroll
                for (int j = 0; j < 4; j++) s[i][j] += a[i] * bb[j];
        }
        __syncthreads();   // all K reads done; KPt can be overwritten

        // write scaled+masked S^T into KPt as Pt[j][i]
#pragma unroll
        for (int j = 0; j < 4; j++)
#pragma unroll
            for (int i = 0; i < 4; i++) {
                int qi = qi0 + ty * 4 + i;
                int kj = k0 + tx * 4 + j;
                float v = (kj <= qi) ? s[i][j] * scale : -3.0e38f;
                KPt[(tx * 4 + j) * 68 + ty * 4 + i] = v;
            }
        __syncthreads();

        // online-softmax row stats (64 threads, one per row)
        if (tid < 64) {
            int r = tid;
            float mold = mrow[r];
            float mt = mold;
            for (int j = 0; j < 64; j++)
                mt = fmaxf(mt, KPt[j * 68 + r]);
            float alpha = __expf(mold - mt);
            float sum = 0.f;
            for (int j = 0; j < 64; j++) {
                float p = __expf(KPt[j * 68 + r] - mt);
                KPt[j * 68 + r] = p;
                sum += p;
            }
            mrow[r] = mt;
            lrow[r] = lrow[r] * alpha + sum;
            arow[r] = alpha;
        }
        __syncthreads();

        // O = O*alpha + P @ V
        float al[4];
#pragma unroll
        for (int i = 0; i < 4; i++) al[i] = arow[ty * 4 + i];
#pragma unroll
        for (int i = 0; i < 4; i++)
#pragma unroll
            for (int j = 0; j < 4; j++) o[i][j] *= al[i];
#pragma unroll 8
        for (int j = 0; j < 64; j++) {
            float4 pv = *(const float4*)&KPt[j * 68 + ty * 4];
            float4 vv = *(const float4*)&Vs[j * 64 + tx * 4];
            float p[4]  = {pv.x, pv.y, pv.z, pv.w};
            float vb[4] = {vv.x, vv.y, vv.z, vv.w};
#pragma unroll
            for (int i = 0; i < 4; i++)
#pragma unroll
                for (int jj = 0; jj < 4; jj++) o[i][jj] += p[i] * vb[jj];
        }
        __syncthreads();   // guard KPt/Vs overwrite next iter
    }

    // normalize + write
    float linv[4];
#pragma unroll
    for (int i = 0; i < 4; i++) linv[i] = 1.f / lrow[ty * 4 + i];
#pragma unroll
    for (int i = 0; i < 4; i++) {
        int row = qi0 + ty * 4 + i;
        float4 v = make_float4(o[i][0] * linv[i], o[i][1] * linv[i],
                               o[i][2] * linv[i], o[i][3] * linv[i]);
        *(float4*)&out[(size_t)(b * T + row) * D + (size_t)h * DH + tx * 4] = v;
    }
}

// ---------------------------------------------------------------------------
extern "C" void kernel_launch(void* const* d_in, const int* in_sizes, int n_in,
                              void* d_out, int out_size)
{
    const float* x      = (const float*)d_in[0];
    const float* w_attn = (const float*)d_in[1];
    const float* b_attn = (const float*)d_in[2];
    const float* w_proj = (const float*)d_in[3];
    const float* b_proj = (const float*)d_in[4];
    float* out = (float*)d_out;

    float *qkv = nullptr, *att = nullptr;
    cudaGetSymbolAddress((void**)&qkv, g_qkv);
    cudaGetSymbolAddress((void**)&att, g_att);

    const int smem_flash = (64 * 64 + 64 * 68 + 64 * 64 + 3 * 64) * sizeof(float);
    cudaFuncSetAttribute(flash_attn,
                         cudaFuncAttributeMaxDynamicSharedMemorySize, smem_flash);

    // 1) QKV projection: [4096,1024] @ [1024,3072] + b
    dim3 g1(D3 / 128, M / 128);
    sgemm_bias<<<g1, 256>>>(x, w_attn, b_attn, qkv, M, D3, D);

    // 2) causal flash attention
    dim3 g2(T / 64, H, B);
    flash_attn<<<g2, 256, smem_flash>>>(qkv, att);

    // 3) output projection: [4096,1024] @ [1024,1024] + b
    dim3 g3(D / 128, M / 128);
    sgemm_bias<<<g3, 256>>>(att, w_proj, b_proj, out, M, D, D);
}

// round 3
// speedup vs baseline: 1.6026x; 1.6026x over previous
#include <cuda_runtime.h>
#include <math.h>

namespace {
constexpr int B  = 2;
constexpr int T  = 2048;
constexpr int D  = 1024;
constexpr int H  = 16;
constexpr int DH = 64;
constexpr int D3 = 3 * D;
constexpr int M  = B * T;      // 4096
}

// Scratch (allocation-free rule: __device__ globals)
__device__ float g_qkv[(size_t)M * D3];   // [M, 3D]
__device__ float g_att[(size_t)M * D];    // [M, D]

__device__ __forceinline__ unsigned f2tf32(float x) {
    unsigned r;
    asm("cvt.rna.tf32.f32 %0, %1;" : "=r"(r) : "f"(x));
    return r;
}

// ---------------------------------------------------------------------------
// C[M,N] = A[M,K] @ W[K,N] + bias[N]
// tf32 mma.sync m16n8k8. BM=128, BN=128, BK=16, 256 threads (8 warps, 2x4),
// warp tile 64x32 (4x4 mma tiles). Double-buffered smem, conflict-free frags.
// ---------------------------------------------------------------------------
__global__ __launch_bounds__(256) void gemm_tf32(
    const float* __restrict__ A, const float* __restrict__ W,
    const float* __restrict__ bias, float* __restrict__ C,
    int Mm, int Nn, int Kk)
{
    __shared__ float As[2][128][20];   // [m][k], pad 16->20: frag loads conflict-free
    __shared__ float Bs[2][16][136];   // [k][n], pad 128->136: frag loads conflict-free

    const int tid  = threadIdx.x;
    const int lane = tid & 31;
    const int wid  = tid >> 5;
    const int gid  = lane >> 2;        // 0..7
    const int tig  = lane & 3;         // 0..3
    const int wm   = wid & 1;          // 0..1
    const int wn   = wid >> 1;         // 0..3
    const int m_base = wm * 64;
    const int n_base = wn * 32;

    const int m0 = blockIdx.y * 128;
    const int n0 = blockIdx.x * 128;

    // global staging indices
    const int arow = tid >> 2;          // + 64*e
    const int ac4  = (tid & 3) * 4;
    const int brow = tid >> 5;          // + 8*e
    const int bc4  = (tid & 31) * 4;

    float acc[4][4][4];
#pragma unroll
    for (int mt = 0; mt < 4; mt++)
#pragma unroll
        for (int nt = 0; nt < 4; nt++)
#pragma unroll
            for (int r = 0; r < 4; r++) acc[mt][nt][r] = 0.f;

    // ---- prologue: stage tile 0 ----
#pragma unroll
    for (int e = 0; e < 2; e++) {
        float4 v = *(const float4*)&A[(size_t)(m0 + arow + 64 * e) * Kk + ac4];
        float* p = &As[0][arow + 64 * e][ac4];
        p[0] = __uint_as_float(f2tf32(v.x));
        p[1] = __uint_as_float(f2tf32(v.y));
        p[2] = __uint_as_float(f2tf32(v.z));
        p[3] = __uint_as_float(f2tf32(v.w));
        float4 w = *(const float4*)&W[(size_t)(brow + 8 * e) * Nn + n0 + bc4];
        float* q = &Bs[0][brow + 8 * e][bc4];
        q[0] = __uint_as_float(f2tf32(w.x));
        q[1] = __uint_as_float(f2tf32(w.y));
        q[2] = __uint_as_float(f2tf32(w.z));
        q[3] = __uint_as_float(f2tf32(w.w));
    }
    __syncthreads();

    const int niter = Kk / 16;
    int cur = 0;

    for (int it = 0; it < niter; it++) {
        // prefetch next tile into regs
        float4 pa[2], pw[2];
        if (it + 1 < niter) {
            int k0 = (it + 1) * 16;
#pragma unroll
            for (int e = 0; e < 2; e++) {
                pa[e] = *(const float4*)&A[(size_t)(m0 + arow + 64 * e) * Kk + k0 + ac4];
                pw[e] = *(const float4*)&W[(size_t)(k0 + brow + 8 * e) * Nn + n0 + bc4];
            }
        }

        // compute 2 k-steps of 8
#pragma unroll
        for (int ks = 0; ks < 2; ks++) {
            const int kk = ks * 8;
            unsigned a[4][4], b[4][2];
#pragma unroll
            for (int mt = 0; mt < 4; mt++) {
                const int mr = m_base + mt * 16 + gid;
                a[mt][0] = __float_as_uint(As[cur][mr][kk + tig]);
                a[mt][1] = __float_as_uint(As[cur][mr + 8][kk + tig]);
                a[mt][2] = __float_as_uint(As[cur][mr][kk + tig + 4]);
                a[mt][3] = __float_as_uint(As[cur][mr + 8][kk + tig + 4]);
            }
#pragma unroll
            for (int nt = 0; nt < 4; nt++) {
                const int nc = n_base + nt * 8 + gid;
                b[nt][0] = __float_as_uint(Bs[cur][kk + tig][nc]);
                b[nt][1] = __float_as_uint(Bs[cur][kk + tig + 4][nc]);
            }
#pragma unroll
            for (int mt = 0; mt < 4; mt++)
#pragma unroll
                for (int nt = 0; nt < 4; nt++) {
                    asm volatile(
                        "mma.sync.aligned.m16n8k8.row.col.f32.tf32.tf32.f32 "
                        "{%0,%1,%2,%3}, {%4,%5,%6,%7}, {%8,%9}, {%0,%1,%2,%3};"
                        : "+f"(acc[mt][nt][0]), "+f"(acc[mt][nt][1]),
                          "+f"(acc[mt][nt][2]), "+f"(acc[mt][nt][3])
                        : "r"(a[mt][0]), "r"(a[mt][1]), "r"(a[mt][2]), "r"(a[mt][3]),
                          "r"(b[nt][0]), "r"(b[nt][1]));
                }
        }

        // stage next tile
        if (it + 1 < niter) {
            const int nxt = cur ^ 1;
#pragma unroll
            for (int e = 0; e < 2; e++) {
                float* p = &As[nxt][arow + 64 * e][ac4];
                p[0] = __uint_as_float(f2tf32(pa[e].x));
                p[1] = __uint_as_float(f2tf32(pa[e].y));
                p[2] = __uint_as_float(f2tf32(pa[e].z));
                p[3] = __uint_as_float(f2tf32(pa[e].w));
                float* q = &Bs[nxt][brow + 8 * e][bc4];
                q[0] = __uint_as_float(f2tf32(pw[e].x));
                q[1] = __uint_as_float(f2tf32(pw[e].y));
                q[2] = __uint_as_float(f2tf32(pw[e].z));
                q[3] = __uint_as_float(f2tf32(pw[e].w));
            }
            __syncthreads();
            cur = nxt;
        }
    }

    // ---- epilogue: bias + store (float2 per mma c-pair) ----
#pragma unroll
    for (int nt = 0; nt < 4; nt++) {
        const int c = n0 + n_base + nt * 8 + 2 * tig;
        const float bx = bias[c], by = bias[c + 1];
#pragma unroll
        for (int mt = 0; mt < 4; mt++) {
            const int r0 = m0 + m_base + mt * 16 + gid;
            float2 v0 = make_float2(acc[mt][nt][0] + bx, acc[mt][nt][1] + by);
            float2 v1 = make_float2(acc[mt][nt][2] + bx, acc[mt][nt][3] + by);
            *(float2*)&C[(size_t)r0 * Nn + c]       = v0;
            *(float2*)&C[(size_t)(r0 + 8) * Nn + c] = v1;
        }
    }
}

// ---------------------------------------------------------------------------
// Flash attention, fp32, causal. One CTA per (b, h, 64-query tile). Bk = 64.
// ---------------------------------------------------------------------------
__global__ __launch_bounds__(256) void flash_attn(
    const float* __restrict__ qkv, float* __restrict__ out)
{
    extern __shared__ float sm[];
    float* Qt   = sm;                 // [64][64]   Qt[d*64 + i]
    float* KPt  = Qt + 64 * 64;       // [64][68]   Kt[d][j] -> Pt[j][i]
    float* Vs   = KPt + 64 * 68;      // [64][64]   Vs[j][d]
    float* mrow = Vs + 64 * 64;       // [64]
    float* lrow = mrow + 64;          // [64]
    float* arow = lrow + 64;          // [64] alpha

    const int tid = threadIdx.x;
    const int tx = tid & 15, ty = tid >> 4;
    const int qt = blockIdx.x, h = blockIdx.y, b = blockIdx.z;
    const int qi0 = qt * 64;
    const float scale = 0.125f;       // 1/sqrt(64)

    const size_t base = (size_t)(b * T) * D3 + (size_t)h * DH;

#pragma unroll
    for (int e = 0; e < 4; e++) {
        int ff  = tid + 256 * e;
        int row = ff >> 4;
        int c4  = (ff & 15) * 4;
        float4 v = *(const float4*)&qkv[base + (size_t)(qi0 + row) * D3 + c4];
        Qt[(c4 + 0) * 64 + row] = v.x;
        Qt[(c4 + 1) * 64 + row] = v.y;
        Qt[(c4 + 2) * 64 + row] = v.z;
        Qt[(c4 + 3) * 64 + row] = v.w;
    }
    if (tid < 64) { mrow[tid] = -3.0e38f; lrow[tid] = 0.f; }

    float o[4][4];
#pragma unroll
    for (int i = 0; i < 4; i++)
#pragma unroll
        for (int j = 0; j < 4; j++) o[i][j] = 0.f;

    __syncthreads();

    for (int k0 = 0; k0 <= qi0; k0 += 64) {
#pragma unroll
        for (int e = 0; e < 4; e++) {
            int ff  = tid + 256 * e;
            int row = ff >> 4;
            int c4  = (ff & 15) * 4;
            size_t g = base + (size_t)(k0 + row) * D3 + c4;
            float4 kv = *(const float4*)&qkv[g + D];       // K
            KPt[(c4 + 0) * 68 + row] = kv.x;
            KPt[(c4 + 1) * 68 + row] = kv.y;
            KPt[(c4 + 2) * 68 + row] = kv.z;
            KPt[(c4 + 3) * 68 + row] = kv.w;
            float4 vv = *(const float4*)&qkv[g + 2 * D];   // V
            *(float4*)&Vs[row * 64 + c4] = vv;
        }
        __syncthreads();

        float s[4][4];
#pragma unroll
        for (int i = 0; i < 4; i++)
#pragma unroll
            for (int j = 0; j < 4; j++) s[i][j] = 0.f;
#pragma unroll 8
        for (int kk = 0; kk < 64; kk++) {
            float4 qa = *(const float4*)&Qt[kk * 64 + ty * 4];
            float4 kb = *(const float4*)&KPt[kk * 68 + tx * 4];
            float a[4] = {qa.x, qa.y, qa.z, qa.w};
            float bb[4] = {kb.x, kb.y, kb.z, kb.w};
#pragma unroll
            for (int i = 0; i < 4; i++)
#pragma unroll
                for (int j = 0; j < 4; j++) s[i][j] += a[i] * bb[j];
        }
        __syncthreads();

#pragma unroll
        for (int j = 0; j < 4; j++)
#pragma unroll
            for (int i = 0; i < 4; i++) {
                int qi = qi0 + ty * 4 + i;
                int kj = k0 + tx * 4 + j;
                float v = (kj <= qi) ? s[i][j] * scale : -3.0e38f;
                KPt[(tx * 4 + j) * 68 + ty * 4 + i] = v;
            }
        __syncthreads();

        if (tid < 64) {
            int r = tid;
            float mold = mrow[r];
            float mt = mold;
            for (int j = 0; j < 64; j++)
                mt = fmaxf(mt, KPt[j * 68 + r]);
            float alpha = __expf(mold - mt);
            float sum = 0.f;
            for (int j = 0; j < 64; j++) {
                float p = __expf(KPt[j * 68 + r] - mt);
                KPt[j * 68 + r] = p;
                sum += p;
            }
            mrow[r] = mt;
            lrow[r] = lrow[r] * alpha + sum;
            arow[r] = alpha;
        }
        __syncthreads();

        float al[4];
#pragma unroll
        for (int i = 0; i < 4; i++) al[i] = arow[ty * 4 + i];
#pragma unroll
        for (int i = 0; i < 4; i++)
#pragma unroll
            for (int j = 0; j < 4; j++) o[i][j] *= al[i];
#pragma unroll 8
        for (int j = 0; j < 64; j++) {
            float4 pv = *(const float4*)&KPt[j * 68 + ty * 4];
            float4 vv = *(const float4*)&Vs[j * 64 + tx * 4];
            float p[4]  = {pv.x, pv.y, pv.z, pv.w};
            float vb[4] = {vv.x, vv.y, vv.z, vv.w};
#pragma unroll
            for (int i = 0; i < 4; i++)
#pragma unroll
                for (int jj = 0; jj < 4; jj++) o[i][jj] += p[i] * vb[jj];
        }
        __syncthreads();
    }

    float linv[4];
#pragma unroll
    for (int i = 0; i < 4; i++) linv[i] = 1.f / lrow[ty * 4 + i];
#pragma unroll
    for (int i = 0; i < 4; i++) {
        int row = qi0 + ty * 4 + i;
        float4 v = make_float4(o[i][0] * linv[i], o[i][1] * linv[i],
                               o[i][2] * linv[i], o[i][3] * linv[i]);
        *(float4*)&out[(size_t)(b * T + row) * D + (size_t)h * DH + tx * 4] = v;
    }
}

// ---------------------------------------------------------------------------
extern "C" void kernel_launch(void* const* d_in, const int* in_sizes, int n_in,
                              void* d_out, int out_size)
{
    const float* x      = (const float*)d_in[0];
    const float* w_attn = (const float*)d_in[1];
    const float* b_attn = (const float*)d_in[2];
    const float* w_proj = (const float*)d_in[3];
    const float* b_proj = (const float*)d_in[4];
    float* out = (float*)d_out;

    float *qkv = nullptr, *att = nullptr;
    cudaGetSymbolAddress((void**)&qkv, g_qkv);
    cudaGetSymbolAddress((void**)&att, g_att);

    const int smem_flash = (64 * 64 + 64 * 68 + 64 * 64 + 3 * 64) * sizeof(float);
    cudaFuncSetAttribute(flash_attn,
                         cudaFuncAttributeMaxDynamicSharedMemorySize, smem_flash);

    // 1) QKV projection: [4096,1024] @ [1024,3072] + b  (tf32 tensor cores)
    dim3 g1(D3 / 128, M / 128);
    gemm_tf32<<<g1, 256>>>(x, w_attn, b_attn, qkv, M, D3, D);

    // 2) causal flash attention
    dim3 g2(T / 64, H, B);
    flash_attn<<<g2, 256, smem_flash>>>(qkv, att);

    // 3) output projection: [4096,1024] @ [1024,1024] + b  (tf32 tensor cores)
    dim3 g3(D / 128, M / 128);
    gemm_tf32<<<g3, 256>>>(att, w_proj, b_proj, out, M, D, D);
}